// round 1
// baseline (speedup 1.0000x reference)
#include <cuda_runtime.h>
#include <cuda_bf16.h>
#include <math.h>

// Problem constants (fixed-shape problem)
#define NMAX 50048
#define EMAX 800000
#define DD   128

// ---------------- device scratch (no allocations allowed) ----------------
__device__ int   g_cnt[NMAX];
__device__ int   g_rowptr[NMAX + 2];
__device__ int   g_wcur[NMAX];
__device__ int   g_eid[EMAX];
__device__ float g_w0[EMAX];
__device__ float g_w1[EMAX];
__device__ float g_w2[EMAX];
__device__ float g_ssum0[NMAX];
__device__ float g_ssum1[NMAX];
__device__ float g_ssum2[NMAX];
__device__ float g_agg[50000 * 384];
__device__ float g_c[50000 * 384];
__device__ float g_ctx[50000 * 128];
__device__ float g_h[50000 * 128];
__device__ float g_gi[50000 * 384];
__device__ float g_gh[50000 * 384];
__device__ int   g_chunk[64];
__device__ int   g_chunkoff[64];

// ---------------- init ----------------
__global__ void k_init(int N) {
    int i = blockIdx.x * blockDim.x + threadIdx.x;
    if (i < N) {
        g_cnt[i] = 0;
        g_ssum0[i] = 0.f; g_ssum1[i] = 0.f; g_ssum2[i] = 0.f;
    }
}

// ---------------- edge pass 1: histogram + exp + exp-sums ----------------
__global__ void k_edge1(const int* __restrict__ dst,
                        const float* __restrict__ l1,
                        const float* __restrict__ l2,
                        const float* __restrict__ l3, int E) {
    int e = blockIdx.x * blockDim.x + threadIdx.x;
    if (e >= E) return;
    int d = dst[e];
    atomicAdd(&g_cnt[d], 1);
    float w0 = __expf(l1[e]);
    float w1 = __expf(l2[e]);
    float w2 = __expf(l3[e]);
    g_w0[e] = w0; g_w1[e] = w1; g_w2[e] = w2;
    atomicAdd(&g_ssum0[d], w0);
    atomicAdd(&g_ssum1[d], w1);
    atomicAdd(&g_ssum2[d], w2);
}

// ---------------- scan (two-level) ----------------
__global__ void k_scan1(int N) {
    __shared__ int sh[1024];
    int t = threadIdx.x;
    int n = blockIdx.x * 1024 + t;
    int v = (n < N) ? g_cnt[n] : 0;
    sh[t] = v;
    __syncthreads();
#pragma unroll
    for (int off = 1; off < 1024; off <<= 1) {
        int x = (t >= off) ? sh[t - off] : 0;
        __syncthreads();
        sh[t] += x;
        __syncthreads();
    }
    if (n < N) g_rowptr[n] = sh[t] - v;  // exclusive within chunk
    if (t == 1023) g_chunk[blockIdx.x] = sh[1023];
}

__global__ void k_scan2(int nch) {
    __shared__ int sh[64];
    int t = threadIdx.x;
    if (t < nch) sh[t] = g_chunk[t];
    __syncthreads();
    if (t == 0) {
        int run = 0;
        for (int i = 0; i < nch; i++) { int tmp = sh[i]; sh[i] = run; run += tmp; }
    }
    __syncthreads();
    if (t < nch) g_chunkoff[t] = sh[t];
}

__global__ void k_scan3(int N, int E) {
    int n = blockIdx.x * 1024 + threadIdx.x;
    if (n < N) {
        int v = g_rowptr[n] + g_chunkoff[blockIdx.x];
        g_rowptr[n] = v;
        g_wcur[n] = v;
    }
    if (n == 0) g_rowptr[N] = E;
}

// ---------------- edge pass 2: scatter edge ids ----------------
__global__ void k_edge2(const int* __restrict__ dst, int E) {
    int e = blockIdx.x * blockDim.x + threadIdx.x;
    if (e >= E) return;
    int d = dst[e];
    int p = atomicAdd(&g_wcur[d], 1);
    g_eid[p] = e;
}

// ---------------- gather: agg_i[n] = sum_e a_i(e) * ef_i[e] ----------------
// one warp per node, lane handles 4 floats (float4) of the 128-dim row
__global__ void k_gather(const float4* __restrict__ ef1,
                         const float4* __restrict__ ef2,
                         const float4* __restrict__ ef3, int N) {
    int warp = blockIdx.x * 8 + (threadIdx.x >> 5);
    int lane = threadIdx.x & 31;
    if (warp >= N) return;
    int s = g_rowptr[warp];
    int eend = g_rowptr[warp + 1];
    float s0 = g_ssum0[warp], s1 = g_ssum1[warp], s2 = g_ssum2[warp];
    float inv0 = (s0 > 0.f) ? 1.f / s0 : 0.f;
    float inv1 = (s1 > 0.f) ? 1.f / s1 : 0.f;
    float inv2 = (s2 > 0.f) ? 1.f / s2 : 0.f;
    float4 a0 = {0, 0, 0, 0}, a1 = {0, 0, 0, 0}, a2 = {0, 0, 0, 0};
    for (int k = s; k < eend; k++) {
        int e = g_eid[k];
        float w0 = g_w0[e] * inv0;
        float w1 = g_w1[e] * inv1;
        float w2 = g_w2[e] * inv2;
        float4 v0 = ef1[e * 32 + lane];
        float4 v1 = ef2[e * 32 + lane];
        float4 v2 = ef3[e * 32 + lane];
        a0.x += w0 * v0.x; a0.y += w0 * v0.y; a0.z += w0 * v0.z; a0.w += w0 * v0.w;
        a1.x += w1 * v1.x; a1.y += w1 * v1.y; a1.z += w1 * v1.z; a1.w += w1 * v1.w;
        a2.x += w2 * v2.x; a2.y += w2 * v2.y; a2.z += w2 * v2.z; a2.w += w2 * v2.w;
    }
    float4* out = reinterpret_cast<float4*>(g_agg) + warp * 96;
    out[lane]      = a0;
    out[32 + lane] = a1;
    out[64 + lane] = a2;
}

// ---------------- generic tiled SGEMM: C[M, cols] = A[M,K] @ B[K,cols] ----------------
// BM=BN=128, BK=32. EPI: 0 = +bias; 1 = elu(x + bias*flag)
template <int KTOT, int EPI, bool CONCAT3>
__global__ __launch_bounds__(256)
void gemm_k(const float* __restrict__ A0, const float* __restrict__ A1,
            const float* __restrict__ A2, int lda,
            const float* __restrict__ B, int ldb,
            const float* __restrict__ bias, const float* __restrict__ flag_s,
            float* __restrict__ C, int ldc, int M) {
    __shared__ float As[32][129];
    __shared__ float Bs[32][132];
    const int t = threadIdx.x;
    const int tx = t & 15, ty = t >> 4;
    const int row0 = blockIdx.x * 128;
    const int coff = blockIdx.y * 128;

    float acc[8][8];
#pragma unroll
    for (int i = 0; i < 8; i++)
#pragma unroll
        for (int j = 0; j < 8; j++) acc[i][j] = 0.f;

    for (int k0 = 0; k0 < KTOT; k0 += 32) {
        // load A tile (128 rows x 32 k), store transposed As[k][m]
#pragma unroll
        for (int i = 0; i < 4; i++) {
            int lin = t + i * 256;        // float4 index, 0..1023
            int r = lin >> 3;             // 0..127
            int kk = (lin & 7) << 2;      // 0,4,...,28
            int grow = row0 + r;
            float4 v = {0, 0, 0, 0};
            if (grow < M) {
                int kg = k0 + kk;
                const float* src;
                if (CONCAT3) {
                    const float* Ap = (kg < 128) ? A0 : ((kg < 256) ? A1 : A2);
                    src = Ap + grow * 128 + (kg & 127);
                } else {
                    src = A0 + grow * lda + kg;
                }
                v = *reinterpret_cast<const float4*>(src);
            }
            As[kk + 0][r] = v.x; As[kk + 1][r] = v.y;
            As[kk + 2][r] = v.z; As[kk + 3][r] = v.w;
        }
        // load B tile (32 k x 128 cols)
#pragma unroll
        for (int i = 0; i < 4; i++) {
            int lin = t + i * 256;
            int kr = lin >> 5;            // 0..31
            int nn = (lin & 31) << 2;     // 0..124
            float4 v = *reinterpret_cast<const float4*>(B + (k0 + kr) * ldb + coff + nn);
            *reinterpret_cast<float4*>(&Bs[kr][nn]) = v;
        }
        __syncthreads();
#pragma unroll
        for (int k = 0; k < 32; k++) {
            float ra[8], rb[8];
#pragma unroll
            for (int i = 0; i < 8; i++) ra[i] = As[k][ty * 8 + i];
#pragma unroll
            for (int j = 0; j < 8; j++) rb[j] = Bs[k][tx * 8 + j];
#pragma unroll
            for (int i = 0; i < 8; i++)
#pragma unroll
                for (int j = 0; j < 8; j++) acc[i][j] += ra[i] * rb[j];
        }
        __syncthreads();
    }
    // epilogue
#pragma unroll
    for (int i = 0; i < 8; i++) {
        int row = row0 + ty * 8 + i;
        if (row >= M) break;
        float fl = 1.f;
        if (EPI == 1) fl = (flag_s[row] > 0.f) ? 1.f : 0.f;
#pragma unroll
        for (int j = 0; j < 8; j++) {
            int col = coff + tx * 8 + j;
            float v;
            if (EPI == 1) {
                v = acc[i][j] + bias[col] * fl;
                v = (v > 0.f) ? v : expm1f(v);
            } else {
                v = acc[i][j] + bias[col];
            }
            C[row * ldc + col] = v;
        }
    }
}

// ---------------- GRU gates + relu ----------------
__global__ void k_gates(float* __restrict__ out, int N) {
    int t = blockIdx.x * blockDim.x + threadIdx.x;
    if (t >= N * 128) return;
    int n = t >> 7, i = t & 127;
    const float* gin = g_gi + n * 384;
    const float* ghn = g_gh + n * 384;
    float r = 1.f / (1.f + __expf(-(gin[i] + ghn[i])));
    float z = 1.f / (1.f + __expf(-(gin[128 + i] + ghn[128 + i])));
    float ng = tanhf(gin[256 + i] + r * ghn[256 + i]);
    float hv = g_h[t];
    float hn = (1.f - z) * ng + z * hv;
    out[t] = fmaxf(hn, 0.f);
}

// ---------------- launch ----------------
extern "C" void kernel_launch(void* const* d_in, const int* in_sizes, int n_in,
                              void* d_out, int out_size) {
    const int*   dst = (const int*)d_in[0];
    const float* l1  = (const float*)d_in[1];
    const float* l2  = (const float*)d_in[2];
    const float* l3  = (const float*)d_in[3];
    const float* ef1 = (const float*)d_in[4];
    const float* ef2 = (const float*)d_in[5];
    const float* ef3 = (const float*)d_in[6];
    const float* nf1 = (const float*)d_in[7];
    const float* nf2 = (const float*)d_in[8];
    const float* nf3 = (const float*)d_in[9];
    const float* W1  = (const float*)d_in[10];
    const float* b1  = (const float*)d_in[11];
    const float* W2  = (const float*)d_in[12];
    const float* b2  = (const float*)d_in[13];
    const float* W3  = (const float*)d_in[14];
    const float* b3  = (const float*)d_in[15];
    const float* Wa  = (const float*)d_in[16];
    const float* ba  = (const float*)d_in[17];
    const float* Wn  = (const float*)d_in[18];
    const float* bn  = (const float*)d_in[19];
    const float* Wih = (const float*)d_in[20];
    const float* bih = (const float*)d_in[21];
    const float* Whh = (const float*)d_in[22];
    const float* bhh = (const float*)d_in[23];

    const int E = in_sizes[0];
    const int N = in_sizes[7] / 128;

    float *p_agg, *p_c, *p_ctx, *p_h, *p_gi, *p_gh, *p_s0, *p_s1, *p_s2;
    cudaGetSymbolAddress((void**)&p_agg, g_agg);
    cudaGetSymbolAddress((void**)&p_c, g_c);
    cudaGetSymbolAddress((void**)&p_ctx, g_ctx);
    cudaGetSymbolAddress((void**)&p_h, g_h);
    cudaGetSymbolAddress((void**)&p_gi, g_gi);
    cudaGetSymbolAddress((void**)&p_gh, g_gh);
    cudaGetSymbolAddress((void**)&p_s0, g_ssum0);
    cudaGetSymbolAddress((void**)&p_s1, g_ssum1);
    cudaGetSymbolAddress((void**)&p_s2, g_ssum2);
    const float* p_s[3] = {p_s0, p_s1, p_s2};
    const float* Ws[3] = {W1, W2, W3};
    const float* bs[3] = {b1, b2, b3};

    const int nch = (N + 1023) / 1024;
    const int mtiles = (N + 127) / 128;

    k_init<<<(N + 255) / 256, 256>>>(N);
    k_edge1<<<(E + 255) / 256, 256>>>(dst, l1, l2, l3, E);
    k_scan1<<<nch, 1024>>>(N);
    k_scan2<<<1, 64>>>(nch);
    k_scan3<<<nch, 1024>>>(N, E);
    k_edge2<<<(E + 255) / 256, 256>>>(dst, E);
    k_gather<<<(N + 7) / 8, 256>>>((const float4*)ef1, (const float4*)ef2,
                                   (const float4*)ef3, N);

    // G1: c_j = elu(agg_j @ W_j + b_j * flag_j)   (3x [N,128]@[128,128])
    for (int j = 0; j < 3; j++) {
        gemm_k<128, 1, false><<<dim3(mtiles, 1), 256>>>(
            p_agg + j * 128, nullptr, nullptr, 384,
            Ws[j], 128, bs[j], p_s[j],
            p_c + j * 128, 384, N);
    }
    // G2a: ctx = c @ Wa + ba   ([N,384]@[384,128])
    gemm_k<384, 0, false><<<dim3(mtiles, 1), 256>>>(
        p_c, nullptr, nullptr, 384, Wa, 128, ba, nullptr, p_ctx, 128, N);
    // G2b: h = [nf1,nf2,nf3] @ Wn + bn   ([N,384]@[384,128], concat gather)
    gemm_k<384, 0, true><<<dim3(mtiles, 1), 256>>>(
        nf1, nf2, nf3, 128, Wn, 128, bn, nullptr, p_h, 128, N);
    // G3a: gi = ctx @ W_ih + b_ih   ([N,128]@[128,384], 3 col tiles)
    gemm_k<128, 0, false><<<dim3(mtiles, 3), 256>>>(
        p_ctx, nullptr, nullptr, 128, Wih, 384, bih, nullptr, p_gi, 384, N);
    // G3b: gh = h @ W_hh + b_hh
    gemm_k<128, 0, false><<<dim3(mtiles, 3), 256>>>(
        p_h, nullptr, nullptr, 128, Whh, 384, bhh, nullptr, p_gh, 384, N);

    k_gates<<<(N * 128 + 255) / 256, 256>>>((float*)d_out, N);
}

// round 2
// speedup vs baseline: 1.7762x; 1.7762x over previous
#include <cuda_runtime.h>
#include <cuda_bf16.h>
#include <math.h>

// Problem constants (fixed-shape problem)
#define NMAX 50048
#define EMAX 800000

// ---------------- device scratch (no allocations allowed) ----------------
__device__ int    g_cnt[NMAX];
__device__ int    g_rowptr[NMAX + 2];
__device__ int    g_wcur[NMAX];
__device__ int    g_eid[EMAX];
__device__ float  g_w0[EMAX];
__device__ float  g_w1[EMAX];
__device__ float  g_w2[EMAX];
__device__ float4 g_wp[EMAX];          // normalized (w0,w1,w2,0) in CSR order
__device__ float  g_ssum0[NMAX];       // after scan3: holds 1/sum (or 0)
__device__ float  g_ssum1[NMAX];
__device__ float  g_ssum2[NMAX];
__device__ float  g_agg[50000 * 384];
__device__ float  g_c[50000 * 384];
__device__ float  g_ctx[50000 * 128];
__device__ float  g_h[50000 * 128];
__device__ float  g_gi[50000 * 384];
__device__ float  g_gh[50000 * 384];
__device__ int    g_chunk[64];
__device__ int    g_chunkoff[64];

// ---------------- init ----------------
__global__ void k_init(int N) {
    int i = blockIdx.x * blockDim.x + threadIdx.x;
    if (i < N) {
        g_cnt[i] = 0;
        g_ssum0[i] = 0.f; g_ssum1[i] = 0.f; g_ssum2[i] = 0.f;
    }
}

// ---------------- edge pass 1: histogram + exp + exp-sums ----------------
__global__ void k_edge1(const int* __restrict__ dst,
                        const float* __restrict__ l1,
                        const float* __restrict__ l2,
                        const float* __restrict__ l3, int E) {
    int e = blockIdx.x * blockDim.x + threadIdx.x;
    if (e >= E) return;
    int d = dst[e];
    atomicAdd(&g_cnt[d], 1);
    float w0 = __expf(l1[e]);
    float w1 = __expf(l2[e]);
    float w2 = __expf(l3[e]);
    g_w0[e] = w0; g_w1[e] = w1; g_w2[e] = w2;
    atomicAdd(&g_ssum0[d], w0);
    atomicAdd(&g_ssum1[d], w1);
    atomicAdd(&g_ssum2[d], w2);
}

// ---------------- scan (two-level) ----------------
__global__ void k_scan1(int N) {
    __shared__ int sh[1024];
    int t = threadIdx.x;
    int n = blockIdx.x * 1024 + t;
    int v = (n < N) ? g_cnt[n] : 0;
    sh[t] = v;
    __syncthreads();
#pragma unroll
    for (int off = 1; off < 1024; off <<= 1) {
        int x = (t >= off) ? sh[t - off] : 0;
        __syncthreads();
        sh[t] += x;
        __syncthreads();
    }
    if (n < N) g_rowptr[n] = sh[t] - v;  // exclusive within chunk
    if (t == 1023) g_chunk[blockIdx.x] = sh[1023];
}

__global__ void k_scan2(int nch) {
    __shared__ int sh[64];
    int t = threadIdx.x;
    if (t < nch) sh[t] = g_chunk[t];
    __syncthreads();
    if (t == 0) {
        int run = 0;
        for (int i = 0; i < nch; i++) { int tmp = sh[i]; sh[i] = run; run += tmp; }
    }
    __syncthreads();
    if (t < nch) g_chunkoff[t] = sh[t];
}

__global__ void k_scan3(int N, int E) {
    int n = blockIdx.x * 1024 + threadIdx.x;
    if (n < N) {
        int v = g_rowptr[n] + g_chunkoff[blockIdx.x];
        g_rowptr[n] = v;
        g_wcur[n] = v;
        // replace sums with inverses (0 for empty nodes)
        float s0 = g_ssum0[n]; g_ssum0[n] = (s0 > 0.f) ? 1.f / s0 : 0.f;
        float s1 = g_ssum1[n]; g_ssum1[n] = (s1 > 0.f) ? 1.f / s1 : 0.f;
        float s2 = g_ssum2[n]; g_ssum2[n] = (s2 > 0.f) ? 1.f / s2 : 0.f;
    }
    if (n == 0) g_rowptr[N] = E;
}

// ---------------- edge pass 2: scatter edge ids + normalized packed weights ----
__global__ void k_edge2(const int* __restrict__ dst, int E) {
    int e = blockIdx.x * blockDim.x + threadIdx.x;
    if (e >= E) return;
    int d = dst[e];
    int p = atomicAdd(&g_wcur[d], 1);
    g_eid[p] = e;
    float4 w;
    w.x = g_w0[e] * g_ssum0[d];
    w.y = g_w1[e] * g_ssum1[d];
    w.z = g_w2[e] * g_ssum2[d];
    w.w = 0.f;
    g_wp[p] = w;
}

// ---------------- gather: agg_i[n] = sum_e a_i(e) * ef_i[e] ----------------
// one warp per node, lane handles 4 floats (float4) of the 128-dim row
__global__ void k_gather(const float4* __restrict__ ef1,
                         const float4* __restrict__ ef2,
                         const float4* __restrict__ ef3, int N) {
    int warp = blockIdx.x * 8 + (threadIdx.x >> 5);
    int lane = threadIdx.x & 31;
    if (warp >= N) return;
    int s = g_rowptr[warp];
    int eend = g_rowptr[warp + 1];
    float4 a0 = {0, 0, 0, 0}, a1 = {0, 0, 0, 0}, a2 = {0, 0, 0, 0};
    int k = s;
    // 4-way batched: front-load independent eid/weight loads for MLP
    for (; k + 4 <= eend; k += 4) {
        int e0 = g_eid[k], e1 = g_eid[k + 1], e2 = g_eid[k + 2], e3 = g_eid[k + 3];
        float4 wA = g_wp[k], wB = g_wp[k + 1], wC = g_wp[k + 2], wD = g_wp[k + 3];
        float4 u0 = ef1[e0 * 32 + lane], u1 = ef1[e1 * 32 + lane];
        float4 u2 = ef1[e2 * 32 + lane], u3 = ef1[e3 * 32 + lane];
        float4 v0 = ef2[e0 * 32 + lane], v1 = ef2[e1 * 32 + lane];
        float4 v2 = ef2[e2 * 32 + lane], v3 = ef2[e3 * 32 + lane];
        float4 x0 = ef3[e0 * 32 + lane], x1 = ef3[e1 * 32 + lane];
        float4 x2 = ef3[e2 * 32 + lane], x3 = ef3[e3 * 32 + lane];
        a0.x += wA.x * u0.x + wB.x * u1.x + wC.x * u2.x + wD.x * u3.x;
        a0.y += wA.x * u0.y + wB.x * u1.y + wC.x * u2.y + wD.x * u3.y;
        a0.z += wA.x * u0.z + wB.x * u1.z + wC.x * u2.z + wD.x * u3.z;
        a0.w += wA.x * u0.w + wB.x * u1.w + wC.x * u2.w + wD.x * u3.w;
        a1.x += wA.y * v0.x + wB.y * v1.x + wC.y * v2.x + wD.y * v3.x;
        a1.y += wA.y * v0.y + wB.y * v1.y + wC.y * v2.y + wD.y * v3.y;
        a1.z += wA.y * v0.z + wB.y * v1.z + wC.y * v2.z + wD.y * v3.z;
        a1.w += wA.y * v0.w + wB.y * v1.w + wC.y * v2.w + wD.y * v3.w;
        a2.x += wA.z * x0.x + wB.z * x1.x + wC.z * x2.x + wD.z * x3.x;
        a2.y += wA.z * x0.y + wB.z * x1.y + wC.z * x2.y + wD.z * x3.y;
        a2.z += wA.z * x0.z + wB.z * x1.z + wC.z * x2.z + wD.z * x3.z;
        a2.w += wA.z * x0.w + wB.z * x1.w + wC.z * x2.w + wD.z * x3.w;
    }
    for (; k < eend; k++) {
        int e = g_eid[k];
        float4 w = g_wp[k];
        float4 u = ef1[e * 32 + lane];
        float4 v = ef2[e * 32 + lane];
        float4 x = ef3[e * 32 + lane];
        a0.x += w.x * u.x; a0.y += w.x * u.y; a0.z += w.x * u.z; a0.w += w.x * u.w;
        a1.x += w.y * v.x; a1.y += w.y * v.y; a1.z += w.y * v.z; a1.w += w.y * v.w;
        a2.x += w.z * x.x; a2.y += w.z * x.y; a2.z += w.z * x.z; a2.w += w.z * x.w;
    }
    float4* out = reinterpret_cast<float4*>(g_agg) + warp * 96;
    out[lane]      = a0;
    out[32 + lane] = a1;
    out[64 + lane] = a2;
}

// ---------------- TF32 tensor-core GEMM ----------------
// C[M, cols] = A[M,K] @ B[K,cols]; BM=BN=128, BK=32
// EPI: 0 = +bias; 1 = elu(x + bias*flag)
__device__ __forceinline__ unsigned f2tf(float x) {
    unsigned r;
    asm("cvt.rna.tf32.f32 %0, %1;" : "=r"(r) : "f"(x));
    return r;
}

template <int KTOT, int EPI, bool CONCAT3>
__global__ __launch_bounds__(256)
void gemm_tc(const float* __restrict__ A0, const float* __restrict__ A1,
             const float* __restrict__ A2, int lda,
             const float* __restrict__ B, int ldb,
             const float* __restrict__ bias, const float* __restrict__ flag_s,
             float* __restrict__ C, int ldc, int M) {
    __shared__ unsigned As[128][36];   // [m][k], padded
    __shared__ unsigned Bs[32][132];   // [k][n], padded
    const int t = threadIdx.x;
    const int lane = t & 31;
    const int warp = t >> 5;
    const int warpM = warp >> 1;       // 0..3  -> 32 rows each
    const int warpN = warp & 1;        // 0..1  -> 64 cols each
    const int row0 = blockIdx.x * 128;
    const int coff = blockIdx.y * 128;

    float acc[2][8][4];
#pragma unroll
    for (int i = 0; i < 2; i++)
#pragma unroll
        for (int j = 0; j < 8; j++)
#pragma unroll
            for (int q = 0; q < 4; q++) acc[i][j][q] = 0.f;

    const int ar = lane >> 2, ac = lane & 3;   // A frag base
    const int bk = lane & 3, bn = lane >> 2;   // B frag base

    for (int k0 = 0; k0 < KTOT; k0 += 32) {
        // load A tile (128 rows x 32 k)
#pragma unroll
        for (int i = 0; i < 4; i++) {
            int lin = t + i * 256;        // float4 index, 0..1023
            int r = lin >> 3;             // 0..127
            int kk = (lin & 7) << 2;      // 0,4,...,28
            int grow = row0 + r;
            float4 v = {0, 0, 0, 0};
            if (grow < M) {
                int kg = k0 + kk;
                const float* src;
                if (CONCAT3) {
                    const float* Ap = (kg < 128) ? A0 : ((kg < 256) ? A1 : A2);
                    src = Ap + grow * 128 + (kg & 127);
                } else {
                    src = A0 + grow * lda + kg;
                }
                v = *reinterpret_cast<const float4*>(src);
            }
            As[r][kk + 0] = f2tf(v.x); As[r][kk + 1] = f2tf(v.y);
            As[r][kk + 2] = f2tf(v.z); As[r][kk + 3] = f2tf(v.w);
        }
        // load B tile (32 k x 128 cols)
#pragma unroll
        for (int i = 0; i < 4; i++) {
            int lin = t + i * 256;
            int kr = lin >> 5;            // 0..31
            int nn = (lin & 31) << 2;     // 0..124
            float4 v = *reinterpret_cast<const float4*>(B + (k0 + kr) * ldb + coff + nn);
            Bs[kr][nn + 0] = f2tf(v.x); Bs[kr][nn + 1] = f2tf(v.y);
            Bs[kr][nn + 2] = f2tf(v.z); Bs[kr][nn + 3] = f2tf(v.w);
        }
        __syncthreads();
#pragma unroll
        for (int kk = 0; kk < 32; kk += 8) {
            unsigned af[2][4];
#pragma unroll
            for (int mi = 0; mi < 2; mi++) {
                int rb = warpM * 32 + mi * 16;
                af[mi][0] = As[rb + ar][kk + ac];
                af[mi][1] = As[rb + ar + 8][kk + ac];
                af[mi][2] = As[rb + ar][kk + ac + 4];
                af[mi][3] = As[rb + ar + 8][kk + ac + 4];
            }
            unsigned bf[8][2];
#pragma unroll
            for (int ni = 0; ni < 8; ni++) {
                int nb = warpN * 64 + ni * 8;
                bf[ni][0] = Bs[kk + bk][nb + bn];
                bf[ni][1] = Bs[kk + bk + 4][nb + bn];
            }
#pragma unroll
            for (int mi = 0; mi < 2; mi++)
#pragma unroll
                for (int ni = 0; ni < 8; ni++) {
                    asm volatile(
                        "mma.sync.aligned.m16n8k8.row.col.f32.tf32.tf32.f32 "
                        "{%0,%1,%2,%3}, {%4,%5,%6,%7}, {%8,%9}, {%0,%1,%2,%3};"
                        : "+f"(acc[mi][ni][0]), "+f"(acc[mi][ni][1]),
                          "+f"(acc[mi][ni][2]), "+f"(acc[mi][ni][3])
                        : "r"(af[mi][0]), "r"(af[mi][1]), "r"(af[mi][2]), "r"(af[mi][3]),
                          "r"(bf[ni][0]), "r"(bf[ni][1]));
                }
        }
        __syncthreads();
    }

    // epilogue
#pragma unroll
    for (int mi = 0; mi < 2; mi++) {
        int rA = row0 + warpM * 32 + mi * 16 + (lane >> 2);
        int rB = rA + 8;
        float flA = 1.f, flB = 1.f;
        if (EPI == 1) {
            flA = (rA < M && flag_s[rA] > 0.f) ? 1.f : 0.f;
            flB = (rB < M && flag_s[rB] > 0.f) ? 1.f : 0.f;
        }
#pragma unroll
        for (int ni = 0; ni < 8; ni++) {
            int col = coff + warpN * 64 + ni * 8 + (lane & 3) * 2;
            float b0 = bias[col], b1 = bias[col + 1];
            if (rA < M) {
                float v0, v1;
                if (EPI == 1) {
                    v0 = acc[mi][ni][0] + b0 * flA;
                    v1 = acc[mi][ni][1] + b1 * flA;
                    v0 = (v0 > 0.f) ? v0 : expm1f(v0);
                    v1 = (v1 > 0.f) ? v1 : expm1f(v1);
                } else {
                    v0 = acc[mi][ni][0] + b0;
                    v1 = acc[mi][ni][1] + b1;
                }
                *reinterpret_cast<float2*>(&C[rA * ldc + col]) = make_float2(v0, v1);
            }
            if (rB < M) {
                float v2, v3;
                if (EPI == 1) {
                    v2 = acc[mi][ni][2] + b0 * flB;
                    v3 = acc[mi][ni][3] + b1 * flB;
                    v2 = (v2 > 0.f) ? v2 : expm1f(v2);
                    v3 = (v3 > 0.f) ? v3 : expm1f(v3);
                } else {
                    v2 = acc[mi][ni][2] + b0;
                    v3 = acc[mi][ni][3] + b1;
                }
                *reinterpret_cast<float2*>(&C[rB * ldc + col]) = make_float2(v2, v3);
            }
        }
    }
}

// ---------------- GRU gates + relu ----------------
__global__ void k_gates(float* __restrict__ out, int N) {
    int t = blockIdx.x * blockDim.x + threadIdx.x;
    if (t >= N * 128) return;
    int n = t >> 7, i = t & 127;
    const float* gin = g_gi + n * 384;
    const float* ghn = g_gh + n * 384;
    float r = 1.f / (1.f + __expf(-(gin[i] + ghn[i])));
    float z = 1.f / (1.f + __expf(-(gin[128 + i] + ghn[128 + i])));
    float ng = tanhf(gin[256 + i] + r * ghn[256 + i]);
    float hv = g_h[t];
    float hn = (1.f - z) * ng + z * hv;
    out[t] = fmaxf(hn, 0.f);
}

// ---------------- launch ----------------
extern "C" void kernel_launch(void* const* d_in, const int* in_sizes, int n_in,
                              void* d_out, int out_size) {
    const int*   dst = (const int*)d_in[0];
    const float* l1  = (const float*)d_in[1];
    const float* l2  = (const float*)d_in[2];
    const float* l3  = (const float*)d_in[3];
    const float* ef1 = (const float*)d_in[4];
    const float* ef2 = (const float*)d_in[5];
    const float* ef3 = (const float*)d_in[6];
    const float* nf1 = (const float*)d_in[7];
    const float* nf2 = (const float*)d_in[8];
    const float* nf3 = (const float*)d_in[9];
    const float* W1  = (const float*)d_in[10];
    const float* b1  = (const float*)d_in[11];
    const float* W2  = (const float*)d_in[12];
    const float* b2  = (const float*)d_in[13];
    const float* W3  = (const float*)d_in[14];
    const float* b3  = (const float*)d_in[15];
    const float* Wa  = (const float*)d_in[16];
    const float* ba  = (const float*)d_in[17];
    const float* Wn  = (const float*)d_in[18];
    const float* bn  = (const float*)d_in[19];
    const float* Wih = (const float*)d_in[20];
    const float* bih = (const float*)d_in[21];
    const float* Whh = (const float*)d_in[22];
    const float* bhh = (const float*)d_in[23];

    const int E = in_sizes[0];
    const int N = in_sizes[7] / 128;

    float *p_agg, *p_c, *p_ctx, *p_h, *p_gi, *p_gh, *p_s0, *p_s1, *p_s2;
    cudaGetSymbolAddress((void**)&p_agg, g_agg);
    cudaGetSymbolAddress((void**)&p_c, g_c);
    cudaGetSymbolAddress((void**)&p_ctx, g_ctx);
    cudaGetSymbolAddress((void**)&p_h, g_h);
    cudaGetSymbolAddress((void**)&p_gi, g_gi);
    cudaGetSymbolAddress((void**)&p_gh, g_gh);
    cudaGetSymbolAddress((void**)&p_s0, g_ssum0);
    cudaGetSymbolAddress((void**)&p_s1, g_ssum1);
    cudaGetSymbolAddress((void**)&p_s2, g_ssum2);
    const float* p_s[3] = {p_s0, p_s1, p_s2};
    const float* Ws[3] = {W1, W2, W3};
    const float* bs[3] = {b1, b2, b3};

    const int nch = (N + 1023) / 1024;
    const int mtiles = (N + 127) / 128;

    k_init<<<(N + 255) / 256, 256>>>(N);
    k_edge1<<<(E + 255) / 256, 256>>>(dst, l1, l2, l3, E);
    k_scan1<<<nch, 1024>>>(N);
    k_scan2<<<1, 64>>>(nch);
    k_scan3<<<nch, 1024>>>(N, E);
    k_edge2<<<(E + 255) / 256, 256>>>(dst, E);
    k_gather<<<(N + 7) / 8, 256>>>((const float4*)ef1, (const float4*)ef2,
                                   (const float4*)ef3, N);

    // G1: c_j = elu(agg_j @ W_j + b_j * flag_j)   (3x [N,128]@[128,128])
    for (int j = 0; j < 3; j++) {
        gemm_tc<128, 1, false><<<dim3(mtiles, 1), 256>>>(
            p_agg + j * 128, nullptr, nullptr, 384,
            Ws[j], 128, bs[j], p_s[j],
            p_c + j * 128, 384, N);
    }
    // G2a: ctx = c @ Wa + ba   ([N,384]@[384,128])
    gemm_tc<384, 0, false><<<dim3(mtiles, 1), 256>>>(
        p_c, nullptr, nullptr, 384, Wa, 128, ba, nullptr, p_ctx, 128, N);
    // G2b: h = [nf1,nf2,nf3] @ Wn + bn   ([N,384]@[384,128], concat gather)
    gemm_tc<384, 0, true><<<dim3(mtiles, 1), 256>>>(
        nf1, nf2, nf3, 128, Wn, 128, bn, nullptr, p_h, 128, N);
    // G3a: gi = ctx @ W_ih + b_ih   ([N,128]@[128,384], 3 col tiles)
    gemm_tc<128, 0, false><<<dim3(mtiles, 3), 256>>>(
        p_ctx, nullptr, nullptr, 128, Wih, 384, bih, nullptr, p_gi, 384, N);
    // G3b: gh = h @ W_hh + b_hh
    gemm_tc<128, 0, false><<<dim3(mtiles, 3), 256>>>(
        p_h, nullptr, nullptr, 128, Whh, 384, bhh, nullptr, p_gh, 384, N);

    k_gates<<<(N * 128 + 255) / 256, 256>>>((float*)d_out, N);
}